// round 7
// baseline (speedup 1.0000x reference)
#include <cuda_runtime.h>
#include <cuda_bf16.h>
#include <cstdint>

// Problem constants
#define NB   64
#define TT   1024
#define EE   256
#define HH   128
#define G3   384          // 3*H
#define GALL 768          // both directions
#define MROWS (NB*TT)     // 65536
#define BOTTLE 32

// ---------------- scratch (static device globals; no runtime alloc) ----------
__device__ float g_wcomb[GALL * EE];          // [768][256] combined W_ih (tf32-rna bits)
__device__ float g_bcomb[GALL];               // [768] combined b_ih (full f32)
__device__ float g_xc[(size_t)MROWS * EE];    // x pre-converted to tf32-rna bits
__device__ float g_gx[(size_t)MROWS * GALL];  // [65536][768] input gate preacts
__device__ float g_hsf[(size_t)MROWS * HH];   // forward hidden states  [m][u]
__device__ float g_hsb[(size_t)MROWS * HH];   // backward hidden states [m][u]

// ---------------- helpers ----------------------------------------------------
__device__ __forceinline__ float sigm_f(float x) {
    return __fdividef(1.f, 1.f + __expf(-x));
}
__device__ __forceinline__ float tanh_f(float x) {
    return __fdividef(2.f, 1.f + __expf(-2.f * x)) - 1.f;
}
__device__ __forceinline__ float cvt_tf32_f(float f) {
    uint32_t r;
    asm("cvt.rna.tf32.f32 %0, %1;" : "=r"(r) : "f"(f));
    return __uint_as_float(r);
}
__device__ __forceinline__ void mma_tf32(float* c, const uint32_t* a, const uint32_t* b) {
    asm volatile(
        "mma.sync.aligned.m16n8k8.row.col.f32.tf32.tf32.f32 "
        "{%0,%1,%2,%3}, {%4,%5,%6,%7}, {%8,%9}, {%0,%1,%2,%3};"
        : "+f"(c[0]), "+f"(c[1]), "+f"(c[2]), "+f"(c[3])
        : "r"(a[0]), "r"(a[1]), "r"(a[2]), "r"(a[3]), "r"(b[0]), "r"(b[1]));
}
__device__ __forceinline__ uint32_t smem_u32(const void* p) {
    uint32_t a;
    asm("{ .reg .u64 t; cvta.to.shared.u64 t, %1; cvt.u32.u64 %0, t; }"
        : "=r"(a) : "l"(p));
    return a;
}
__device__ __forceinline__ void cp_async16(uint32_t s, const void* g) {
    asm volatile("cp.async.cg.shared.global [%0], [%1], 16;" :: "r"(s), "l"(g));
}
__device__ __forceinline__ void cp_commit() {
    asm volatile("cp.async.commit_group;");
}

// ---------------- kernel 0a: pack W (tf32-rna) + bias -------------------------
__global__ void pack_weights(const float* __restrict__ w_ih_f,
                             const float* __restrict__ b_ih_f,
                             const float* __restrict__ w_ih_b,
                             const float* __restrict__ b_ih_b) {
    int i = blockIdx.x * blockDim.x + threadIdx.x;
    if (i < GALL * EE) {
        int g = i / EE;
        float v = (g < G3) ? w_ih_f[i] : w_ih_b[i - G3 * EE];
        g_wcomb[i] = cvt_tf32_f(v);
    }
    if (i < GALL) {
        g_bcomb[i] = (i < G3) ? b_ih_f[i] : b_ih_b[i - G3];
    }
}

// ---------------- kernel 0b: pack X (tf32-rna) --------------------------------
__global__ void pack_xc(const float* __restrict__ X) {
    size_t i4 = (size_t)blockIdx.x * blockDim.x + threadIdx.x;
    if (i4 < (size_t)MROWS * EE / 4) {
        float4 v = reinterpret_cast<const float4*>(X)[i4];
        float4 o = {cvt_tf32_f(v.x), cvt_tf32_f(v.y),
                    cvt_tf32_f(v.z), cvt_tf32_f(v.w)};
        reinterpret_cast<float4*>(g_xc)[i4] = o;
    }
}

// ---------------- kernel 1: gx GEMM, tf32 mma + cp.async double buffer --------
#define GBM 128
#define GBN 128
#define GBK 16
#define TSTR 20
#define NK_ITERS (EE / GBK)   // 16
__global__ __launch_bounds__(256, 2) void gemm_gx_mma(void) {
    __shared__ __align__(16) float As[2][GBM][TSTR];
    __shared__ __align__(16) float Bs[2][GBN][TSTR];

    const int tid = threadIdx.x;
    const int lane = tid & 31;
    const int warp = tid >> 5;
    const int wm = warp & 3;
    const int wn = warp >> 2;
    const int m0 = blockIdx.x * GBM;
    const int n0 = blockIdx.y * GBN;

    const int lr = tid >> 1;
    const int lc = (tid & 1) * 2;

    float c[2][8][4];
#pragma unroll
    for (int mt = 0; mt < 2; mt++)
#pragma unroll
        for (int nt = 0; nt < 8; nt++)
#pragma unroll
            for (int q = 0; q < 4; q++) c[mt][nt][q] = 0.f;

    const float* gA = g_xc + (size_t)m0 * EE;
    const float* gB = g_wcomb + (size_t)n0 * EE;

    auto issue = [&](int it, int s) {
        const int k0 = it * GBK;
#pragma unroll
        for (int cc = 0; cc < 2; cc++) {
            uint32_t sa = smem_u32(&As[s][lr][(lc + cc) * 4]);
            cp_async16(sa, gA + (size_t)lr * EE + k0 + (lc + cc) * 4);
        }
#pragma unroll
        for (int cc = 0; cc < 2; cc++) {
            uint32_t sb = smem_u32(&Bs[s][lr][(lc + cc) * 4]);
            cp_async16(sb, gB + (size_t)lr * EE + k0 + (lc + cc) * 4);
        }
    };

    issue(0, 0);
    cp_commit();

    for (int it = 0; it < NK_ITERS; it++) {
        const int s = it & 1;
        if (it + 1 < NK_ITERS) {
            issue(it + 1, s ^ 1);
            cp_commit();
            asm volatile("cp.async.wait_group 1;");
        } else {
            asm volatile("cp.async.wait_group 0;");
        }
        __syncthreads();

#pragma unroll
        for (int kt = 0; kt < 2; kt++) {
            const int kc = kt * 8 + (lane & 3);
            uint32_t a[2][4];
            uint32_t b[8][2];
#pragma unroll
            for (int mt = 0; mt < 2; mt++) {
                int m = wm * 32 + mt * 16 + (lane >> 2);
                a[mt][0] = __float_as_uint(As[s][m][kc]);
                a[mt][1] = __float_as_uint(As[s][m + 8][kc]);
                a[mt][2] = __float_as_uint(As[s][m][kc + 4]);
                a[mt][3] = __float_as_uint(As[s][m + 8][kc + 4]);
            }
#pragma unroll
            for (int nt = 0; nt < 8; nt++) {
                int n = wn * 64 + nt * 8 + (lane >> 2);
                b[nt][0] = __float_as_uint(Bs[s][n][kc]);
                b[nt][1] = __float_as_uint(Bs[s][n][kc + 4]);
            }
#pragma unroll
            for (int mt = 0; mt < 2; mt++)
#pragma unroll
                for (int nt = 0; nt < 8; nt++) mma_tf32(c[mt][nt], a[mt], b[nt]);
        }
        __syncthreads();
    }

#pragma unroll
    for (int mt = 0; mt < 2; mt++) {
        int m = m0 + wm * 32 + mt * 16 + (lane >> 2);
#pragma unroll
        for (int nt = 0; nt < 8; nt++) {
            int g = n0 + wn * 64 + nt * 8 + (lane & 3) * 2;
            float b0v = g_bcomb[g];
            float b1v = g_bcomb[g + 1];
            float2 o0 = {c[mt][nt][0] + b0v, c[mt][nt][1] + b1v};
            float2 o1 = {c[mt][nt][2] + b0v, c[mt][nt][3] + b1v};
            *reinterpret_cast<float2*>(g_gx + (size_t)m * GALL + g) = o0;
            *reinterpret_cast<float2*>(g_gx + (size_t)(m + 8) * GALL + g) = o1;
        }
    }
}

// ---------------- kernel 2: GRU scan v2 ---------------------------------------
// 384 threads: thread = (gate g in {0:r,1:z,2:n}, u in 0..127).
// Each thread owns the FULL W row (128 regs) -> no partial reduction, no spills
// (register budget 65536/384 = 170/thread).
__global__ __launch_bounds__(384, 1) void gru_scan(
    const float* __restrict__ Whh_f, const float* __restrict__ bhh_f,
    const float* __restrict__ Whh_b, const float* __restrict__ bhh_b) {
    __shared__ __align__(16) float sh_h[HH];
    __shared__ float s_prez[HH];
    __shared__ float s_ghn[HH];
    __shared__ float s_gxn[HH];

    const int tid = threadIdx.x;
    const int g = tid >> 7;           // 0..2 (gate)
    const int u = tid & 127;
    const int blk = blockIdx.x;       // 0..127
    const int n = blk & 63;
    const int dir = blk >> 6;

    const float* Whh = dir ? Whh_b : Whh_f;
    const float* bhh = dir ? bhh_b : bhh_f;
    float* hs_out = dir ? g_hsb : g_hsf;
    const float* gx = g_gx + (size_t)n * TT * GALL + dir * G3 + g * HH + u;

    // full W row for this (gate, u) in registers
    float W[128];
    {
        const float4* wrow = reinterpret_cast<const float4*>(
            Whh + ((size_t)g * HH + u) * HH);
#pragma unroll
        for (int q = 0; q < 32; q++) {
            float4 v = wrow[q];
            W[q * 4 + 0] = v.x;
            W[q * 4 + 1] = v.y;
            W[q * 4 + 2] = v.z;
            W[q * 4 + 3] = v.w;
        }
    }
    const float bias = bhh[g * HH + u];
    float hold = 0.f;
    if (tid < HH) sh_h[tid] = 0.f;
    __syncthreads();

    int t = dir ? (TT - 1) : 0;
    const int dt = dir ? -1 : 1;

    for (int s = 0; s < TT; s++, t += dt) {
        // own gx element for this step (coalesced across the warp)
        const float gv = __ldcs(gx + (size_t)t * GALL);

        // full 128-dot with 4 independent accumulator chains
        float a0 = 0.f, a1 = 0.f, a2 = 0.f, a3 = 0.f;
        const float4* h4 = reinterpret_cast<const float4*>(sh_h);
#pragma unroll
        for (int q = 0; q < 32; q++) {
            float4 hv = h4[q];
            a0 += W[q * 4 + 0] * hv.x;
            a1 += W[q * 4 + 1] * hv.y;
            a2 += W[q * 4 + 2] * hv.z;
            a3 += W[q * 4 + 3] * hv.w;
        }
        const float acc = (a0 + a1) + (a2 + a3);

        if (g == 1) {
            s_prez[u] = gv + acc + bias;
        } else if (g == 2) {
            s_ghn[u] = acc + bias;
            s_gxn[u] = gv;
        }
        const float pre_r = gv + acc + bias;   // meaningful for g==0
        __syncthreads();

        if (g == 0) {
            float r = sigm_f(pre_r);
            float z = sigm_f(s_prez[u]);
            float nn = tanh_f(s_gxn[u] + r * s_ghn[u]);
            float hnew = (1.f - z) * nn + z * hold;
            hold = hnew;
            sh_h[u] = hnew;
            hs_out[((size_t)n * TT + t) * HH + u] = hnew;
        }
        __syncthreads();
    }
}

// ---------------- kernel 3: output projection (staged, proven) ----------------
__global__ __launch_bounds__(256) void proj_kernel(
    const float* __restrict__ wo, const float* __restrict__ bo,
    float* __restrict__ out) {
    __shared__ float hch[256][33];
    __shared__ float wch[32][BOTTLE];

    const int tid = threadIdx.x;
    const int m0 = blockIdx.x * 256;

    float acc[BOTTLE];
#pragma unroll
    for (int b = 0; b < BOTTLE; b++) acc[b] = __ldg(bo + b);

    for (int ch = 0; ch < 8; ch++) {
        const int c0 = ch * 32;
        const float* src = (c0 < HH) ? g_hsf : g_hsb;
        const int ccol0 = (c0 < HH) ? c0 : (c0 - HH);

#pragma unroll
        for (int l = 0; l < 8; l++) {
            int idx = tid + l * 256;
            int r = idx >> 3;
            int f4i = idx & 7;
            float4 v = *reinterpret_cast<const float4*>(
                src + (size_t)(m0 + r) * HH + ccol0 + f4i * 4);
            hch[r][f4i * 4 + 0] = v.x;
            hch[r][f4i * 4 + 1] = v.y;
            hch[r][f4i * 4 + 2] = v.z;
            hch[r][f4i * 4 + 3] = v.w;
        }
        for (int i = tid; i < 32 * BOTTLE; i += 256) {
            int cc = i >> 5;
            int b = i & 31;
            wch[cc][b] = wo[(size_t)b * EE + c0 + cc];
        }
        __syncthreads();

#pragma unroll 8
        for (int cc = 0; cc < 32; cc++) {
            float v = hch[tid][cc];
            const float4* w4 = reinterpret_cast<const float4*>(wch[cc]);
#pragma unroll
            for (int b4 = 0; b4 < 8; b4++) {
                float4 wv = w4[b4];
                acc[b4 * 4 + 0] += v * wv.x;
                acc[b4 * 4 + 1] += v * wv.y;
                acc[b4 * 4 + 2] += v * wv.z;
                acc[b4 * 4 + 3] += v * wv.w;
            }
        }
        __syncthreads();
    }

    float4* dst = reinterpret_cast<float4*>(out + (size_t)(m0 + tid) * BOTTLE);
#pragma unroll
    for (int b4 = 0; b4 < 8; b4++) {
        float4 o = {acc[b4 * 4 + 0], acc[b4 * 4 + 1],
                    acc[b4 * 4 + 2], acc[b4 * 4 + 3]};
        dst[b4] = o;
    }
}

// ---------------- launch ------------------------------------------------------
extern "C" void kernel_launch(void* const* d_in, const int* in_sizes, int n_in,
                              void* d_out, int out_size) {
    const float* x      = (const float*)d_in[0];
    const float* w_ih_f = (const float*)d_in[1];
    const float* w_hh_f = (const float*)d_in[2];
    const float* b_ih_f = (const float*)d_in[3];
    const float* b_hh_f = (const float*)d_in[4];
    const float* w_ih_b = (const float*)d_in[5];
    const float* w_hh_b = (const float*)d_in[6];
    const float* b_ih_b = (const float*)d_in[7];
    const float* b_hh_b = (const float*)d_in[8];
    const float* w_out  = (const float*)d_in[9];
    const float* b_out  = (const float*)d_in[10];
    float* out = (float*)d_out;

    pack_weights<<<GALL, 256>>>(w_ih_f, b_ih_f, w_ih_b, b_ih_b);
    pack_xc<<<MROWS * EE / 4 / 256, 256>>>(x);
    gemm_gx_mma<<<dim3(MROWS / GBM, GALL / GBN), 256>>>();
    gru_scan<<<128, 384>>>(w_hh_f, b_hh_f, w_hh_b, b_hh_b);
    proj_kernel<<<MROWS / 256, 256>>>(w_out, b_out, out);
}

// round 9
// speedup vs baseline: 1.5391x; 1.5391x over previous
#include <cuda_runtime.h>
#include <cuda_bf16.h>
#include <cstdint>

// Problem constants
#define NB   64
#define TT   1024
#define EE   256
#define HH   128
#define G3   384          // 3*H
#define GALL 768          // both directions
#define MROWS (NB*TT)     // 65536
#define BOTTLE 32

// ---------------- scratch (static device globals; no runtime alloc) ----------
__device__ float g_wcomb[GALL * EE];          // [768][256] combined W_ih (tf32-rna bits)
__device__ float g_bcomb[GALL];               // [768] combined b_ih (full f32)
__device__ float g_xc[(size_t)MROWS * EE];    // x pre-converted to tf32-rna bits
__device__ float g_gx[(size_t)MROWS * GALL];  // [65536][768] input gate preacts
__device__ float g_hsf[(size_t)MROWS * HH];   // forward hidden states  [m][u]
__device__ float g_hsb[(size_t)MROWS * HH];   // backward hidden states [m][u]

// ---------------- helpers ----------------------------------------------------
__device__ __forceinline__ float sigm_f(float x) {
    return __fdividef(1.f, 1.f + __expf(-x));
}
__device__ __forceinline__ float tanh_f(float x) {
    return __fdividef(2.f, 1.f + __expf(-2.f * x)) - 1.f;
}
__device__ __forceinline__ float cvt_tf32_f(float f) {
    uint32_t r;
    asm("cvt.rna.tf32.f32 %0, %1;" : "=r"(r) : "f"(f));
    return __uint_as_float(r);
}
__device__ __forceinline__ void mma_tf32(float* c, const uint32_t* a, const uint32_t* b) {
    asm volatile(
        "mma.sync.aligned.m16n8k8.row.col.f32.tf32.tf32.f32 "
        "{%0,%1,%2,%3}, {%4,%5,%6,%7}, {%8,%9}, {%0,%1,%2,%3};"
        : "+f"(c[0]), "+f"(c[1]), "+f"(c[2]), "+f"(c[3])
        : "r"(a[0]), "r"(a[1]), "r"(a[2]), "r"(a[3]), "r"(b[0]), "r"(b[1]));
}
__device__ __forceinline__ uint32_t smem_u32(const void* p) {
    uint32_t a;
    asm("{ .reg .u64 t; cvta.to.shared.u64 t, %1; cvt.u32.u64 %0, t; }"
        : "=r"(a) : "l"(p));
    return a;
}
__device__ __forceinline__ void cp_async16(uint32_t s, const void* g) {
    asm volatile("cp.async.cg.shared.global [%0], [%1], 16;" :: "r"(s), "l"(g));
}
__device__ __forceinline__ void cp_commit() {
    asm volatile("cp.async.commit_group;");
}

// ---------------- kernel 0a: pack W (tf32-rna) + bias -------------------------
__global__ void pack_weights(const float* __restrict__ w_ih_f,
                             const float* __restrict__ b_ih_f,
                             const float* __restrict__ w_ih_b,
                             const float* __restrict__ b_ih_b) {
    int i = blockIdx.x * blockDim.x + threadIdx.x;
    if (i < GALL * EE) {
        int g = i / EE;
        float v = (g < G3) ? w_ih_f[i] : w_ih_b[i - G3 * EE];
        g_wcomb[i] = cvt_tf32_f(v);
    }
    if (i < GALL) {
        g_bcomb[i] = (i < G3) ? b_ih_f[i] : b_ih_b[i - G3];
    }
}

// ---------------- kernel 0b: pack X (tf32-rna) --------------------------------
__global__ void pack_xc(const float* __restrict__ X) {
    size_t i4 = (size_t)blockIdx.x * blockDim.x + threadIdx.x;
    if (i4 < (size_t)MROWS * EE / 4) {
        float4 v = reinterpret_cast<const float4*>(X)[i4];
        float4 o = {cvt_tf32_f(v.x), cvt_tf32_f(v.y),
                    cvt_tf32_f(v.z), cvt_tf32_f(v.w)};
        reinterpret_cast<float4*>(g_xc)[i4] = o;
    }
}

// ---------------- kernel 1: gx GEMM, tf32 mma + cp.async, BK=32 ---------------
// C[65536,768] = Xc @ Wcomb^T.  Tile 128x128, K chunks of 32, 2-stage pipeline.
#define GBM 128
#define GBN 128
#define GBK 32
#define TSTR 36            // smem row stride (floats), conflict-free fragments
#define NK_ITERS (EE / GBK)   // 8
#define GEMM_SMEM (2 * 2 * GBM * TSTR * 4)   // 73728 B (dynamic)
__global__ __launch_bounds__(256, 2) void gemm_gx_mma(void) {
    extern __shared__ float smem_dyn[];
    // layout: As[2][128][TSTR] then Bs[2][128][TSTR]
    float (*As)[GBM][TSTR] = reinterpret_cast<float (*)[GBM][TSTR]>(smem_dyn);
    float (*Bs)[GBM][TSTR] =
        reinterpret_cast<float (*)[GBM][TSTR]>(smem_dyn + 2 * GBM * TSTR);

    const int tid = threadIdx.x;
    const int lane = tid & 31;
    const int warp = tid >> 5;
    const int wm = warp & 3;
    const int wn = warp >> 2;
    const int m0 = blockIdx.x * GBM;
    const int n0 = blockIdx.y * GBN;

    // cp.async mapping: row = tid>>1, 4 chunks of 16B starting at (tid&1)*4
    const int lr = tid >> 1;
    const int lc0 = (tid & 1) * 4;

    float c[2][8][4];
#pragma unroll
    for (int mt = 0; mt < 2; mt++)
#pragma unroll
        for (int nt = 0; nt < 8; nt++)
#pragma unroll
            for (int q = 0; q < 4; q++) c[mt][nt][q] = 0.f;

    const float* gA = g_xc + (size_t)m0 * EE;
    const float* gB = g_wcomb + (size_t)n0 * EE;

    auto issue = [&](int it, int s) {
        const int k0 = it * GBK;
#pragma unroll
        for (int cc = 0; cc < 4; cc++) {
            uint32_t sa = smem_u32(&As[s][lr][(lc0 + cc) * 4]);
            cp_async16(sa, gA + (size_t)lr * EE + k0 + (lc0 + cc) * 4);
        }
#pragma unroll
        for (int cc = 0; cc < 4; cc++) {
            uint32_t sb = smem_u32(&Bs[s][lr][(lc0 + cc) * 4]);
            cp_async16(sb, gB + (size_t)lr * EE + k0 + (lc0 + cc) * 4);
        }
    };

    issue(0, 0);
    cp_commit();

    for (int it = 0; it < NK_ITERS; it++) {
        const int s = it & 1;
        if (it + 1 < NK_ITERS) {
            issue(it + 1, s ^ 1);
            cp_commit();
            asm volatile("cp.async.wait_group 1;");
        } else {
            asm volatile("cp.async.wait_group 0;");
        }
        __syncthreads();

#pragma unroll
        for (int kt = 0; kt < 4; kt++) {
            const int kc = kt * 8 + (lane & 3);
            uint32_t a[2][4];
            uint32_t b[8][2];
#pragma unroll
            for (int mt = 0; mt < 2; mt++) {
                int m = wm * 32 + mt * 16 + (lane >> 2);
                a[mt][0] = __float_as_uint(As[s][m][kc]);
                a[mt][1] = __float_as_uint(As[s][m + 8][kc]);
                a[mt][2] = __float_as_uint(As[s][m][kc + 4]);
                a[mt][3] = __float_as_uint(As[s][m + 8][kc + 4]);
            }
#pragma unroll
            for (int nt = 0; nt < 8; nt++) {
                int n = wn * 64 + nt * 8 + (lane >> 2);
                b[nt][0] = __float_as_uint(Bs[s][n][kc]);
                b[nt][1] = __float_as_uint(Bs[s][n][kc + 4]);
            }
#pragma unroll
            for (int mt = 0; mt < 2; mt++)
#pragma unroll
                for (int nt = 0; nt < 8; nt++) mma_tf32(c[mt][nt], a[mt], b[nt]);
        }
        __syncthreads();
    }

#pragma unroll
    for (int mt = 0; mt < 2; mt++) {
        int m = m0 + wm * 32 + mt * 16 + (lane >> 2);
#pragma unroll
        for (int nt = 0; nt < 8; nt++) {
            int g = n0 + wn * 64 + nt * 8 + (lane & 3) * 2;
            float b0v = g_bcomb[g];
            float b1v = g_bcomb[g + 1];
            float2 o0 = {c[mt][nt][0] + b0v, c[mt][nt][1] + b1v};
            float2 o1 = {c[mt][nt][2] + b0v, c[mt][nt][3] + b1v};
            *reinterpret_cast<float2*>(g_gx + (size_t)m * GALL + g) = o0;
            *reinterpret_cast<float2*>(g_gx + (size_t)(m + 8) * GALL + g) = o1;
        }
    }
}

// ---------------- kernel 2: GRU scan (v1, 32-bit offset stepping) -------------
__global__ __launch_bounds__(512, 1) void gru_scan(
    const float* __restrict__ Whh_f, const float* __restrict__ bhh_f,
    const float* __restrict__ Whh_b, const float* __restrict__ bhh_b) {
    __shared__ __align__(16) float sh_h[HH];
    __shared__ __align__(16) float sp[4][3][HH];

    const int tid = threadIdx.x;
    const int u = tid & 127;
    const int jb = tid >> 7;          // 0..3
    const int blk = blockIdx.x;       // 0..127
    const int n = blk & 63;
    const int dir = blk >> 6;

    const float* Whh = dir ? Whh_b : Whh_f;
    const float* bhh = dir ? bhh_b : bhh_f;
    float* hs_base = (dir ? g_hsb : g_hsf) + (size_t)n * TT * HH + u;
    const float* gx_base = g_gx + (size_t)n * TT * GALL + dir * G3 + u;

    float wr[32], wz[32], wn[32];
#pragma unroll
    for (int q = 0; q < 32; q++) {
        int j = jb * 32 + q;
        wr[q] = Whh[(size_t)u * HH + j];
        wz[q] = Whh[(size_t)(HH + u) * HH + j];
        wn[q] = Whh[(size_t)(2 * HH + u) * HH + j];
    }
    float bhr = 0.f, bhz = 0.f, bhn = 0.f, hold = 0.f;
    if (jb == 0) {
        bhr = bhh[u];
        bhz = bhh[HH + u];
        bhn = bhh[2 * HH + u];
        sh_h[u] = 0.f;
    }
    __syncthreads();

    // 32-bit stepped offsets (avoid 64-bit per-step pointer math)
    int goff = dir ? (TT - 1) * GALL : 0;
    int hoff = dir ? (TT - 1) * HH : 0;
    const int gstep = dir ? -GALL : GALL;
    const int hstep = dir ? -HH : HH;

    for (int s = 0; s < TT; s++, goff += gstep, hoff += hstep) {
        float gxr = 0.f, gxz = 0.f, gxn = 0.f;
        if (jb == 0) {
            gxr = __ldcs(gx_base + goff);
            gxz = __ldcs(gx_base + goff + HH);
            gxn = __ldcs(gx_base + goff + 2 * HH);
        }

        float ar = 0.f, az = 0.f, an = 0.f;
        const float4* h4 = reinterpret_cast<const float4*>(sh_h + jb * 32);
#pragma unroll
        for (int q4 = 0; q4 < 8; q4++) {
            float4 hv = h4[q4];
            ar += wr[q4 * 4 + 0] * hv.x; az += wz[q4 * 4 + 0] * hv.x; an += wn[q4 * 4 + 0] * hv.x;
            ar += wr[q4 * 4 + 1] * hv.y; az += wz[q4 * 4 + 1] * hv.y; an += wn[q4 * 4 + 1] * hv.y;
            ar += wr[q4 * 4 + 2] * hv.z; az += wz[q4 * 4 + 2] * hv.z; an += wn[q4 * 4 + 2] * hv.z;
            ar += wr[q4 * 4 + 3] * hv.w; az += wz[q4 * 4 + 3] * hv.w; an += wn[q4 * 4 + 3] * hv.w;
        }
        sp[jb][0][u] = ar;
        sp[jb][1][u] = az;
        sp[jb][2][u] = an;
        __syncthreads();

        if (jb == 0) {
            float ghr = sp[0][0][u] + sp[1][0][u] + sp[2][0][u] + sp[3][0][u] + bhr;
            float ghz = sp[0][1][u] + sp[1][1][u] + sp[2][1][u] + sp[3][1][u] + bhz;
            float ghn = sp[0][2][u] + sp[1][2][u] + sp[2][2][u] + sp[3][2][u] + bhn;
            float r = sigm_f(gxr + ghr);
            float z = sigm_f(gxz + ghz);
            float nn = tanh_f(gxn + r * ghn);
            float hnew = (1.f - z) * nn + z * hold;
            hold = hnew;
            sh_h[u] = hnew;
            hs_base[hoff] = hnew;
        }
        __syncthreads();
    }
}

// ---------------- kernel 3: output projection (staged, proven) ----------------
__global__ __launch_bounds__(256) void proj_kernel(
    const float* __restrict__ wo, const float* __restrict__ bo,
    float* __restrict__ out) {
    __shared__ float hch[256][33];
    __shared__ float wch[32][BOTTLE];

    const int tid = threadIdx.x;
    const int m0 = blockIdx.x * 256;

    float acc[BOTTLE];
#pragma unroll
    for (int b = 0; b < BOTTLE; b++) acc[b] = __ldg(bo + b);

    for (int ch = 0; ch < 8; ch++) {
        const int c0 = ch * 32;
        const float* src = (c0 < HH) ? g_hsf : g_hsb;
        const int ccol0 = (c0 < HH) ? c0 : (c0 - HH);

#pragma unroll
        for (int l = 0; l < 8; l++) {
            int idx = tid + l * 256;
            int r = idx >> 3;
            int f4i = idx & 7;
            float4 v = *reinterpret_cast<const float4*>(
                src + (size_t)(m0 + r) * HH + ccol0 + f4i * 4);
            hch[r][f4i * 4 + 0] = v.x;
            hch[r][f4i * 4 + 1] = v.y;
            hch[r][f4i * 4 + 2] = v.z;
            hch[r][f4i * 4 + 3] = v.w;
        }
        for (int i = tid; i < 32 * BOTTLE; i += 256) {
            int cc = i >> 5;
            int b = i & 31;
            wch[cc][b] = wo[(size_t)b * EE + c0 + cc];
        }
        __syncthreads();

#pragma unroll 8
        for (int cc = 0; cc < 32; cc++) {
            float v = hch[tid][cc];
            const float4* w4 = reinterpret_cast<const float4*>(wch[cc]);
#pragma unroll
            for (int b4 = 0; b4 < 8; b4++) {
                float4 wv = w4[b4];
                acc[b4 * 4 + 0] += v * wv.x;
                acc[b4 * 4 + 1] += v * wv.y;
                acc[b4 * 4 + 2] += v * wv.z;
                acc[b4 * 4 + 3] += v * wv.w;
            }
        }
        __syncthreads();
    }

    float4* dst = reinterpret_cast<float4*>(out + (size_t)(m0 + tid) * BOTTLE);
#pragma unroll
    for (int b4 = 0; b4 < 8; b4++) {
        float4 o = {acc[b4 * 4 + 0], acc[b4 * 4 + 1],
                    acc[b4 * 4 + 2], acc[b4 * 4 + 3]};
        dst[b4] = o;
    }
}

// ---------------- launch ------------------------------------------------------
extern "C" void kernel_launch(void* const* d_in, const int* in_sizes, int n_in,
                              void* d_out, int out_size) {
    const float* x      = (const float*)d_in[0];
    const float* w_ih_f = (const float*)d_in[1];
    const float* w_hh_f = (const float*)d_in[2];
    const float* b_ih_f = (const float*)d_in[3];
    const float* b_hh_f = (const float*)d_in[4];
    const float* w_ih_b = (const float*)d_in[5];
    const float* w_hh_b = (const float*)d_in[6];
    const float* b_ih_b = (const float*)d_in[7];
    const float* b_hh_b = (const float*)d_in[8];
    const float* w_out  = (const float*)d_in[9];
    const float* b_out  = (const float*)d_in[10];
    float* out = (float*)d_out;

    // idempotent, called every time (no static guards)
    cudaFuncSetAttribute(gemm_gx_mma,
                         cudaFuncAttributeMaxDynamicSharedMemorySize, GEMM_SMEM);

    pack_weights<<<GALL, 256>>>(w_ih_f, b_ih_f, w_ih_b, b_ih_b);
    pack_xc<<<MROWS * EE / 4 / 256, 256>>>(x);
    gemm_gx_mma<<<dim3(MROWS / GBM, GALL / GBN), 256, GEMM_SMEM>>>();
    gru_scan<<<128, 512>>>(w_hh_f, b_hh_f, w_hh_b, b_hh_b);
    proj_kernel<<<MROWS / 256, 256>>>(w_out, b_out, out);
}